// round 16
// baseline (speedup 1.0000x reference)
#include <cuda_runtime.h>
#include <cuda_fp16.h>
#include <math.h>
#include <stdint.h>

// SupConLoss fused; Gram via plain fp16 mma.sync (no split). sm_103.
// out = 0.5*ce + 0.5*cl + 0.25*triple (ALPHA=0.5)
// feats L2-normalized => Gram in [-1,1] => fixed softmax shifts exp((g-1)*10),
// exp((g-1)*20). R16 = R15 + k_reduce/final fused into k_main's last block
// (2 kernels total), CE loads vectorized.

#define KD   128
#define NN   4096
#define CLS_MAX 64
#define NJT  32

typedef unsigned long long u64;
typedef unsigned short u16;

__device__ __align__(16) __half g_hbf[NN * KD];   // fp16 feats
__device__ int      g_cnt[CLS_MAX];       // zero-init; re-zeroed by last block
__device__ unsigned g_done;               // zero-init; reset by last block
__device__ float    g_rowCe[NN];
__device__ float    g_accE[NN];           // zeroed by CE threads in k_pre
__device__ float    g_accS[NN];
__device__ float    g_accR[NN];
__device__ unsigned g_accM[NN];           // ordered-uint max of g (diff-label)

// ---------------- helpers ----------------
__device__ __forceinline__ uint32_t smem_u32(const void* p) {
    uint32_t a;
    asm("{ .reg .u64 t; cvta.to.shared.u64 t, %1; cvt.u32.u64 %0, t; }"
        : "=r"(a) : "l"(p));
    return a;
}
__device__ __forceinline__ void cp16(uint32_t s, const void* g) {
    asm volatile("cp.async.ca.shared.global [%0], [%1], 16;" :: "r"(s), "l"(g));
}
__device__ __forceinline__ void ldsm4(uint32_t* r, uint32_t addr) {
    asm volatile("ldmatrix.sync.aligned.m8n8.x4.shared.b16 {%0,%1,%2,%3}, [%4];"
        : "=r"(r[0]), "=r"(r[1]), "=r"(r[2]), "=r"(r[3]) : "r"(addr));
}
__device__ __forceinline__ void mma_f16(float* d, const uint32_t* a, const uint32_t* b) {
    asm volatile("mma.sync.aligned.m16n8k16.row.col.f32.f16.f16.f32 "
        "{%0,%1,%2,%3}, {%4,%5,%6,%7}, {%8,%9}, {%0,%1,%2,%3};"
        : "+f"(d[0]), "+f"(d[1]), "+f"(d[2]), "+f"(d[3])
        : "r"(a[0]), "r"(a[1]), "r"(a[2]), "r"(a[3]), "r"(b[0]), "r"(b[1]));
}
// monotone float<->uint for atomicMax
__device__ __forceinline__ unsigned fenc(float f) {
    unsigned u = __float_as_uint(f);
    return (u & 0x80000000u) ? ~u : (u | 0x80000000u);
}
__device__ __forceinline__ float fdec(unsigned u) {
    return __uint_as_float((u & 0x80000000u) ? (u & 0x7fffffffu) : ~u);
}
#define ENC_NEG2 0x3FFFFFFFu   // fenc(-2.0f)

// smem: A tile 128x(272B) = 34816, B tile 34816; partials overlay A after MMA
#define A_STRIDE  272
#define TILE_SZ   34816
#define SMEM_MAIN 69632

// ---------------------------------------------------------------------------
// Fused prep (normalize + fp16 convert + histogram) and CE (+acc zeroing).
__global__ void __launch_bounds__(256) k_pre(const float* __restrict__ x,
                                             const float* __restrict__ pred,
                                             const int* __restrict__ tgt,
                                             int N, int C) {
    int tid = threadIdx.x;
    if (blockIdx.x < (unsigned)(N / 16)) {
        int r = tid >> 4, l16 = tid & 15;          // 16 threads per row
        int row = blockIdx.x * 16 + r;
        const float4* xr = (const float4*)&x[row * KD + l16 * 8];
        float4 q0 = xr[0], q1 = xr[1];
        float ss = q0.x * q0.x + q0.y * q0.y + q0.z * q0.z + q0.w * q0.w
                 + q1.x * q1.x + q1.y * q1.y + q1.z * q1.z + q1.w * q1.w;
        #pragma unroll
        for (int o = 8; o; o >>= 1) ss += __shfl_xor_sync(0xffffffffu, ss, o);
        float inv = 1.f / fmaxf(sqrtf(ss), 1e-12f);
        float v[8] = {q0.x, q0.y, q0.z, q0.w, q1.x, q1.y, q1.z, q1.w};
        u16 hs[8];
        #pragma unroll
        for (int c = 0; c < 8; c++) {
            __half hb = __float2half(v[c] * inv);
            hs[c] = *(u16*)&hb;
        }
        *(uint4*)&g_hbf[row * KD + l16 * 8] = *(uint4*)&hs[0];
        if (l16 == 0) atomicAdd(&g_cnt[tgt[row]], 1);
    } else {
        int row = (blockIdx.x - N / 16) * 256 + tid;
        if (row >= N) return;
        g_accE[row] = 0.f; g_accS[row] = 0.f; g_accR[row] = 0.f;
        g_accM[row] = ENC_NEG2;
        float v[24];
        int C4 = C >> 2;
        const float4* p4 = (const float4*)(pred + (size_t)row * C);
        for (int i = 0; i < C4; i++) {
            float4 q = p4[i];
            v[i * 4 + 0] = q.x; v[i * 4 + 1] = q.y;
            v[i * 4 + 2] = q.z; v[i * 4 + 3] = q.w;
        }
        for (int c = C4 * 4; c < C; c++) v[c] = pred[(size_t)row * C + c];
        float mx = -1e30f;
        for (int c = 0; c < C; c++) mx = fmaxf(mx, v[c]);
        float e = 0.f;
        for (int c = 0; c < C; c++) e += __expf(v[c] - mx);
        g_rowCe[row] = v[tgt[row]] - mx - logf(e);
    }
}

// ---------------------------------------------------------------------------
// Main Gram pass: 528 triangular blocks (mt<=jt), 256 threads.
// Full K=128 resident in smem. Epilogue fused in registers; merged stats go
// to global atomics. The LAST block finalizes all rows and writes the loss.
__global__ void __launch_bounds__(256, 2) k_main(const int* __restrict__ tgt,
                                                 float* __restrict__ out,
                                                 int N, int C) {
    extern __shared__ __align__(16) char smem[];
    __shared__ int s_il[128], s_jl[128];
    __shared__ unsigned s_last;
    __shared__ float s_cls[CLS_MAX];
    __shared__ float s_red[256];
    uint32_t smBase = smem_u32(smem);
    float4* colPart = (float4*)smem;              // [128 cols][4 wr] (overlay)
    float4* rowPart = (float4*)(smem + 8192);     // [128 rows][2 wc]
    uint32_t T_A = smBase, T_B = smBase + TILE_SZ;

    int tid = threadIdx.x, wid = tid >> 5, lane = tid & 31;
    int wr = wid & 3, wc = wid >> 2;

    int b = blockIdx.x, mt = 0;
    while (b >= NJT - mt) { b -= NJT - mt; mt++; }
    int jt = mt + b;
    int rowBase = mt * 128, jBase = jt * 128;
    bool isDiag = (mt == jt);

    if (tid < 128) s_il[tid] = tgt[rowBase + tid];
    else           s_jl[tid - 128] = tgt[jBase + (tid - 128)];

    // single fill: both full tiles (128 rows x 256B, stride 272)
    #pragma unroll
    for (int i = 0; i < 8; i++) {
        int idx = tid + i * 256;                  // 0..2047
        int row = idx >> 4, seg = idx & 15;
        cp16(T_A + row * A_STRIDE + seg * 16, g_hbf + (rowBase + row) * KD + seg * 8);
        cp16(T_B + row * A_STRIDE + seg * 16, g_hbf + (jBase + row) * KD + seg * 8);
    }
    asm volatile("cp.async.commit_group;" ::: "memory");

    float d[2][8][4];
    #pragma unroll
    for (int mi = 0; mi < 2; mi++)
        #pragma unroll
        for (int ni = 0; ni < 8; ni++)
            #pragma unroll
            for (int e = 0; e < 4; e++) d[mi][ni][e] = 0.f;

    asm volatile("cp.async.wait_group 0;" ::: "memory");
    __syncthreads();

    int lr = lane & 7, s1 = (lane >> 3) & 1, s2 = lane >> 4;

    #pragma unroll
    for (int kb = 0; kb < 128; kb += 16) {
        uint32_t a[2][4], bb[8][2];
        uint32_t aoff = (uint32_t)((wr * 32 + lr + s1 * 8) * A_STRIDE + (kb + s2 * 8) * 2);
        ldsm4(a[0], T_A + aoff);
        ldsm4(a[1], T_A + aoff + 16 * A_STRIDE);
        #pragma unroll
        for (int pr = 0; pr < 4; pr++) {
            uint32_t t[4];
            ldsm4(t, T_B + (uint32_t)((wc * 64 + pr * 16 + lr + s2 * 8) * A_STRIDE
                                      + (kb + s1 * 8) * 2));
            bb[2 * pr][0] = t[0]; bb[2 * pr][1] = t[1];
            bb[2 * pr + 1][0] = t[2]; bb[2 * pr + 1][1] = t[3];
        }
        #pragma unroll
        for (int mi = 0; mi < 2; mi++)
            #pragma unroll
            for (int ni = 0; ni < 8; ni++)
                mma_f16(d[mi][ni], a[mi], bb[ni]);
    }
    __syncthreads();   // tiles dead; smem reused for partials

    // ---- fused register epilogue ----
    int lr4 = lane >> 2, lc2 = lane & 3;
    int il[4];
    #pragma unroll
    for (int s = 0; s < 4; s++) il[s] = s_il[wr * 32 + s * 8 + lr4];

    float rE[4], rS[4], rR[4], rB[4];
    #pragma unroll
    for (int s = 0; s < 4; s++) { rE[s] = 0.f; rS[s] = 0.f; rR[s] = 0.f; rB[s] = -2.f; }

    #pragma unroll
    for (int ni = 0; ni < 8; ni++) {
        int c0 = wc * 64 + ni * 8 + lc2 * 2;
        int jl0 = s_jl[c0], jl1 = s_jl[c0 + 1];
        float cE0 = 0.f, cS0 = 0.f, cR0 = 0.f, cB0 = -2.f;
        float cE1 = 0.f, cS1 = 0.f, cR1 = 0.f, cB1 = -2.f;
        #pragma unroll
        for (int mi = 0; mi < 2; mi++) {
            #pragma unroll
            for (int e = 0; e < 4; e++) {
                int sub = mi * 2 + (e >> 1);
                float g = d[mi][ni][e];
                float e10 = __expf(fmaf(g, 10.f, -10.f));
                int jl = (e & 1) ? jl1 : jl0;
                bool same = (jl == il[sub]);
                bool diag = isDiag && ((c0 + (e & 1)) == (wr * 32 + sub * 8 + lr4));
                if (same) {
                    if (!diag) {
                        rE[sub] += e10; rS[sub] += g;
                        if (e & 1) { cE1 += e10; cS1 += g; }
                        else       { cE0 += e10; cS0 += g; }
                    }
                } else {
                    float e20 = e10 * e10;
                    rR[sub] += e20; rB[sub] = fmaxf(rB[sub], g);
                    if (e & 1) { cR1 += e20; cB1 = fmaxf(cB1, g); }
                    else       { cR0 += e20; cB0 = fmaxf(cB0, g); }
                }
            }
        }
        #pragma unroll
        for (int o = 4; o <= 16; o <<= 1) {
            cE0 += __shfl_xor_sync(0xffffffffu, cE0, o);
            cS0 += __shfl_xor_sync(0xffffffffu, cS0, o);
            cR0 += __shfl_xor_sync(0xffffffffu, cR0, o);
            cB0 = fmaxf(cB0, __shfl_xor_sync(0xffffffffu, cB0, o));
            cE1 += __shfl_xor_sync(0xffffffffu, cE1, o);
            cS1 += __shfl_xor_sync(0xffffffffu, cS1, o);
            cR1 += __shfl_xor_sync(0xffffffffu, cR1, o);
            cB1 = fmaxf(cB1, __shfl_xor_sync(0xffffffffu, cB1, o));
        }
        if (lr4 == 0) {
            colPart[c0 * 4 + wr]       = make_float4(cE0, cS0, cR0, cB0);
            colPart[(c0 + 1) * 4 + wr] = make_float4(cE1, cS1, cR1, cB1);
        }
    }
    #pragma unroll
    for (int s = 0; s < 4; s++) {
        #pragma unroll
        for (int o = 1; o <= 2; o <<= 1) {
            rE[s] += __shfl_xor_sync(0xffffffffu, rE[s], o);
            rS[s] += __shfl_xor_sync(0xffffffffu, rS[s], o);
            rR[s] += __shfl_xor_sync(0xffffffffu, rR[s], o);
            rB[s] = fmaxf(rB[s], __shfl_xor_sync(0xffffffffu, rB[s], o));
        }
    }
    if (lc2 == 0) {
        #pragma unroll
        for (int s = 0; s < 4; s++)
            rowPart[(wr * 32 + s * 8 + lr4) * 2 + wc] = make_float4(rE[s], rS[s], rR[s], rB[s]);
    }
    __syncthreads();
    if (tid < 128) {
        float4 a = rowPart[tid * 2], b2 = rowPart[tid * 2 + 1];
        int row = rowBase + tid;
        atomicAdd(&g_accE[row], a.x + b2.x);
        atomicAdd(&g_accS[row], a.y + b2.y);
        atomicAdd(&g_accR[row], a.z + b2.z);
        atomicMax(&g_accM[row], fenc(fmaxf(a.w, b2.w)));
    } else if (!isDiag) {
        int cc = tid - 128;
        float4 x0 = colPart[cc * 4 + 0], x1 = colPart[cc * 4 + 1];
        float4 x2 = colPart[cc * 4 + 2], x3 = colPart[cc * 4 + 3];
        int row = jBase + cc;
        atomicAdd(&g_accE[row], x0.x + x1.x + x2.x + x3.x);
        atomicAdd(&g_accS[row], x0.y + x1.y + x2.y + x3.y);
        atomicAdd(&g_accR[row], x0.z + x1.z + x2.z + x3.z);
        atomicMax(&g_accM[row], fenc(fmaxf(fmaxf(x0.w, x1.w), fmaxf(x2.w, x3.w))));
    }

    // ---- last-block-done: finalize all rows + loss ----
    __threadfence();
    __syncthreads();
    if (tid == 0) s_last = (atomicAdd(&g_done, 1u) == (unsigned)(gridDim.x - 1));
    __syncthreads();
    if (!s_last) return;

    if (tid < CLS_MAX) s_cls[tid] = 0.f;
    __syncthreads();

    float ceS = 0.f, clS = 0.f;
    #pragma unroll 4
    for (int k = 0; k < NN / 256; k++) {
        int row = tid + k * 256;
        float E = g_accE[row], S = g_accS[row], R = g_accR[row];
        float bmx = fdec(g_accM[row]);
        int lb = tgt[row];
        int cnt = g_cnt[lb];
        float clc = 0.f;
        if (cnt > 1)
            clc = S * 10.f / (float)(cnt - 1) - 10.f - logf(E + 1e-12f);
        float Bmax = fmaxf(0.f, bmx * 20.f);
        float rR = R * expf(20.f - Bmax) + (float)cnt * expf(-Bmax);
        ceS += g_rowCe[row];
        clS += clc;
        atomicAdd(&s_cls[lb], rR);
    }
    s_red[tid] = ceS; __syncthreads();
    for (int s = 128; s; s >>= 1) { if (tid < s) s_red[tid] += s_red[tid + s]; __syncthreads(); }
    float ceSum = s_red[0]; __syncthreads();
    s_red[tid] = clS; __syncthreads();
    for (int s = 128; s; s >>= 1) { if (tid < s) s_red[tid] += s_red[tid + s]; __syncthreads(); }
    float clSum = s_red[0]; __syncthreads();

    if (wid == 0) {
        bool has = (lane < C);
        int   cc = has ? g_cnt[lane] : 0;
        float Rc = has ? s_cls[lane] : 0.f;
        float myc = (float)cc * (float)(N - cc);     // exact: <= 2^24
        float totalR = Rc, total_c = myc;
        #pragma unroll
        for (int o = 16; o; o >>= 1) {
            totalR  += __shfl_xor_sync(0xffffffffu, totalR, o);
            total_c += __shfl_xor_sync(0xffffffffu, total_c, o);
        }
        float ns = total_c - myc;
        unsigned nz = __ballot_sync(0xffffffffu, has && cc > 0 && ns != 0.f);
        bool all_zero = (nz == 0u);
        float term = 0.f;
        if (has && cc > 0) {
            float S = (N - cc > 0) ? (totalR - Rc + (float)cc * (float)N) : 0.f;
            float x = all_zero ? S : S / ((ns == 0.f) ? 1.0f : ns);
            term = (float)cc * logf(x + 1e-12f);
        }
        #pragma unroll
        for (int o = 16; o; o >>= 1) term += __shfl_xor_sync(0xffffffffu, term, o);
        if (lane == 0) {
            float ce_loss = -ceSum / (float)N;
            float cl_loss = -clSum / (float)N;
            float triple  = term / (float)N;
            out[0] = 0.5f * ce_loss + 0.5f * cl_loss + 0.25f * triple;
            g_done = 0;                          // reset for next graph replay
        }
    }
    __syncthreads();
    if (tid < CLS_MAX) g_cnt[tid] = 0;           // leave zeroed for next call
}

// ---------------------------------------------------------------------------
extern "C" void kernel_launch(void* const* d_in, const int* in_sizes, int n_in,
                              void* d_out, int out_size) {
    const float* cls  = (const float*)d_in[0];
    const float* pred = (const float*)d_in[1];
    const int*   tgt  = (const int*)d_in[2];
    int N = in_sizes[2];
    int C = in_sizes[1] / N;
    float* out = (float*)d_out;

    k_pre<<<N / 16 + (N + 255) / 256, 256>>>(cls, pred, tgt, N, C);

    cudaFuncSetAttribute(k_main, cudaFuncAttributeMaxDynamicSharedMemorySize, SMEM_MAIN);
    k_main<<<NJT * (NJT + 1) / 2, 256, SMEM_MAIN>>>(tgt, out, N, C);
}

// round 17
// speedup vs baseline: 1.5603x; 1.5603x over previous
#include <cuda_runtime.h>
#include <cuda_fp16.h>
#include <math.h>
#include <stdint.h>

// SupConLoss fused; Gram via plain fp16 mma.sync (no split). sm_103.
// out = 0.5*ce + 0.5*cl + 0.25*triple (ALPHA=0.5)
// feats L2-normalized => Gram in [-1,1] => fixed softmax shifts exp((g-1)*10),
// exp((g-1)*20). R17 = R15 (best measured) + PDL (programmatic dependent
// launch) on k_main and k_reduce to hide inter-kernel launch latency.

#define KD   128
#define NN   4096
#define CLS_MAX 64
#define NJT  32

typedef unsigned long long u64;
typedef unsigned short u16;

__device__ __align__(16) __half g_hbf[NN * KD];   // fp16 feats
__device__ int      g_cnt[CLS_MAX];       // zero-init; re-zeroed by last block
__device__ unsigned g_done;               // zero-init; reset by last block
__device__ float    g_rowCe[NN];
__device__ float    g_accE[NN];           // zeroed by CE threads in k_pre
__device__ float    g_accS[NN];
__device__ float    g_accR[NN];
__device__ unsigned g_accM[NN];           // ordered-uint max of g (diff-label)
__device__ float    g_blk[128 * 24];      // per-block partials: ce, cl, classR

// ---------------- helpers ----------------
__device__ __forceinline__ void pdl_wait() {
    asm volatile("griddepcontrol.wait;" ::: "memory");
}
__device__ __forceinline__ uint32_t smem_u32(const void* p) {
    uint32_t a;
    asm("{ .reg .u64 t; cvta.to.shared.u64 t, %1; cvt.u32.u64 %0, t; }"
        : "=r"(a) : "l"(p));
    return a;
}
__device__ __forceinline__ void cp16(uint32_t s, const void* g) {
    asm volatile("cp.async.ca.shared.global [%0], [%1], 16;" :: "r"(s), "l"(g));
}
__device__ __forceinline__ void ldsm4(uint32_t* r, uint32_t addr) {
    asm volatile("ldmatrix.sync.aligned.m8n8.x4.shared.b16 {%0,%1,%2,%3}, [%4];"
        : "=r"(r[0]), "=r"(r[1]), "=r"(r[2]), "=r"(r[3]) : "r"(addr));
}
__device__ __forceinline__ void mma_f16(float* d, const uint32_t* a, const uint32_t* b) {
    asm volatile("mma.sync.aligned.m16n8k16.row.col.f32.f16.f16.f32 "
        "{%0,%1,%2,%3}, {%4,%5,%6,%7}, {%8,%9}, {%0,%1,%2,%3};"
        : "+f"(d[0]), "+f"(d[1]), "+f"(d[2]), "+f"(d[3])
        : "r"(a[0]), "r"(a[1]), "r"(a[2]), "r"(a[3]), "r"(b[0]), "r"(b[1]));
}
// monotone float<->uint for atomicMax
__device__ __forceinline__ unsigned fenc(float f) {
    unsigned u = __float_as_uint(f);
    return (u & 0x80000000u) ? ~u : (u | 0x80000000u);
}
__device__ __forceinline__ float fdec(unsigned u) {
    return __uint_as_float((u & 0x80000000u) ? (u & 0x7fffffffu) : ~u);
}
#define ENC_NEG2 0x3FFFFFFFu   // fenc(-2.0f)

// smem: A tile 128x(272B) = 34816, B tile 34816; partials overlay A after MMA
#define A_STRIDE  272
#define TILE_SZ   34816
#define SMEM_MAIN 69632

// ---------------------------------------------------------------------------
// Fused prep (normalize + fp16 convert + histogram) and CE (+acc zeroing).
__global__ void __launch_bounds__(256) k_pre(const float* __restrict__ x,
                                             const float* __restrict__ pred,
                                             const int* __restrict__ tgt,
                                             int N, int C) {
    int tid = threadIdx.x;
    if (blockIdx.x < (unsigned)(N / 16)) {
        int r = tid >> 4, l16 = tid & 15;          // 16 threads per row
        int row = blockIdx.x * 16 + r;
        const float4* xr = (const float4*)&x[row * KD + l16 * 8];
        float4 q0 = xr[0], q1 = xr[1];
        float ss = q0.x * q0.x + q0.y * q0.y + q0.z * q0.z + q0.w * q0.w
                 + q1.x * q1.x + q1.y * q1.y + q1.z * q1.z + q1.w * q1.w;
        #pragma unroll
        for (int o = 8; o; o >>= 1) ss += __shfl_xor_sync(0xffffffffu, ss, o);
        float inv = 1.f / fmaxf(sqrtf(ss), 1e-12f);
        float v[8] = {q0.x, q0.y, q0.z, q0.w, q1.x, q1.y, q1.z, q1.w};
        u16 hs[8];
        #pragma unroll
        for (int c = 0; c < 8; c++) {
            __half hb = __float2half(v[c] * inv);
            hs[c] = *(u16*)&hb;
        }
        *(uint4*)&g_hbf[row * KD + l16 * 8] = *(uint4*)&hs[0];
        if (l16 == 0) atomicAdd(&g_cnt[tgt[row]], 1);
    } else {
        int row = (blockIdx.x - N / 16) * 256 + tid;
        if (row >= N) return;
        // zero per-row accumulators (1:1 row mapping, off the prep path)
        g_accE[row] = 0.f; g_accS[row] = 0.f; g_accR[row] = 0.f;
        g_accM[row] = ENC_NEG2;
        const float* pr = pred + row * C;
        float mx = -1e30f;
        for (int c = 0; c < C; c++) mx = fmaxf(mx, pr[c]);
        float e = 0.f;
        for (int c = 0; c < C; c++) e += __expf(pr[c] - mx);
        g_rowCe[row] = pr[tgt[row]] - mx - logf(e);
    }
}

// ---------------------------------------------------------------------------
// Main Gram pass: 528 triangular blocks (mt<=jt), 256 threads.
// Full K=128 resident in smem (single fill, no pipeline).
// Epilogue fused in registers; merged stats go to global atomics.
__global__ void __launch_bounds__(256, 2) k_main(const int* __restrict__ tgt) {
    extern __shared__ __align__(16) char smem[];
    __shared__ int s_il[128], s_jl[128];
    uint32_t smBase = smem_u32(smem);
    float4* colPart = (float4*)smem;              // [128 cols][4 wr] (overlay)
    float4* rowPart = (float4*)(smem + 8192);     // [128 rows][2 wc]
    uint32_t T_A = smBase, T_B = smBase + TILE_SZ;

    pdl_wait();   // PDL: k_pre's writes (g_hbf, g_cnt, g_acc*) visible after this

    int tid = threadIdx.x, wid = tid >> 5, lane = tid & 31;
    int wr = wid & 3, wc = wid >> 2;

    int b = blockIdx.x, mt = 0;
    while (b >= NJT - mt) { b -= NJT - mt; mt++; }
    int jt = mt + b;
    int rowBase = mt * 128, jBase = jt * 128;
    bool isDiag = (mt == jt);

    if (tid < 128) s_il[tid] = tgt[rowBase + tid];
    else           s_jl[tid - 128] = tgt[jBase + (tid - 128)];

    // single fill: both full tiles (128 rows x 256B, stride 272)
    #pragma unroll
    for (int i = 0; i < 8; i++) {
        int idx = tid + i * 256;                  // 0..2047
        int row = idx >> 4, seg = idx & 15;
        cp16(T_A + row * A_STRIDE + seg * 16, g_hbf + (rowBase + row) * KD + seg * 8);
        cp16(T_B + row * A_STRIDE + seg * 16, g_hbf + (jBase + row) * KD + seg * 8);
    }
    asm volatile("cp.async.commit_group;" ::: "memory");

    float d[2][8][4];
    #pragma unroll
    for (int mi = 0; mi < 2; mi++)
        #pragma unroll
        for (int ni = 0; ni < 8; ni++)
            #pragma unroll
            for (int e = 0; e < 4; e++) d[mi][ni][e] = 0.f;

    asm volatile("cp.async.wait_group 0;" ::: "memory");
    __syncthreads();

    int lr = lane & 7, s1 = (lane >> 3) & 1, s2 = lane >> 4;

    #pragma unroll
    for (int kb = 0; kb < 128; kb += 16) {
        uint32_t a[2][4], bb[8][2];
        uint32_t aoff = (uint32_t)((wr * 32 + lr + s1 * 8) * A_STRIDE + (kb + s2 * 8) * 2);
        ldsm4(a[0], T_A + aoff);
        ldsm4(a[1], T_A + aoff + 16 * A_STRIDE);
        #pragma unroll
        for (int pr = 0; pr < 4; pr++) {
            uint32_t t[4];
            ldsm4(t, T_B + (uint32_t)((wc * 64 + pr * 16 + lr + s2 * 8) * A_STRIDE
                                      + (kb + s1 * 8) * 2));
            bb[2 * pr][0] = t[0]; bb[2 * pr][1] = t[1];
            bb[2 * pr + 1][0] = t[2]; bb[2 * pr + 1][1] = t[3];
        }
        #pragma unroll
        for (int mi = 0; mi < 2; mi++)
            #pragma unroll
            for (int ni = 0; ni < 8; ni++)
                mma_f16(d[mi][ni], a[mi], bb[ni]);
    }
    __syncthreads();   // tiles dead; smem reused for partials

    // ---- fused register epilogue ----
    int lr4 = lane >> 2, lc2 = lane & 3;
    int il[4];
    #pragma unroll
    for (int s = 0; s < 4; s++) il[s] = s_il[wr * 32 + s * 8 + lr4];

    float rE[4], rS[4], rR[4], rB[4];
    #pragma unroll
    for (int s = 0; s < 4; s++) { rE[s] = 0.f; rS[s] = 0.f; rR[s] = 0.f; rB[s] = -2.f; }

    #pragma unroll
    for (int ni = 0; ni < 8; ni++) {
        int c0 = wc * 64 + ni * 8 + lc2 * 2;
        int jl0 = s_jl[c0], jl1 = s_jl[c0 + 1];
        float cE0 = 0.f, cS0 = 0.f, cR0 = 0.f, cB0 = -2.f;
        float cE1 = 0.f, cS1 = 0.f, cR1 = 0.f, cB1 = -2.f;
        #pragma unroll
        for (int mi = 0; mi < 2; mi++) {
            #pragma unroll
            for (int e = 0; e < 4; e++) {
                int sub = mi * 2 + (e >> 1);
                float g = d[mi][ni][e];
                float e10 = __expf(fmaf(g, 10.f, -10.f));
                int jl = (e & 1) ? jl1 : jl0;
                bool same = (jl == il[sub]);
                bool diag = isDiag && ((c0 + (e & 1)) == (wr * 32 + sub * 8 + lr4));
                if (same) {
                    if (!diag) {
                        rE[sub] += e10; rS[sub] += g;
                        if (e & 1) { cE1 += e10; cS1 += g; }
                        else       { cE0 += e10; cS0 += g; }
                    }
                } else {
                    float e20 = e10 * e10;
                    rR[sub] += e20; rB[sub] = fmaxf(rB[sub], g);
                    if (e & 1) { cR1 += e20; cB1 = fmaxf(cB1, g); }
                    else       { cR0 += e20; cB0 = fmaxf(cB0, g); }
                }
            }
        }
        #pragma unroll
        for (int o = 4; o <= 16; o <<= 1) {
            cE0 += __shfl_xor_sync(0xffffffffu, cE0, o);
            cS0 += __shfl_xor_sync(0xffffffffu, cS0, o);
            cR0 += __shfl_xor_sync(0xffffffffu, cR0, o);
            cB0 = fmaxf(cB0, __shfl_xor_sync(0xffffffffu, cB0, o));
            cE1 += __shfl_xor_sync(0xffffffffu, cE1, o);
            cS1 += __shfl_xor_sync(0xffffffffu, cS1, o);
            cR1 += __shfl_xor_sync(0xffffffffu, cR1, o);
            cB1 = fmaxf(cB1, __shfl_xor_sync(0xffffffffu, cB1, o));
        }
        if (lr4 == 0) {
            colPart[c0 * 4 + wr]       = make_float4(cE0, cS0, cR0, cB0);
            colPart[(c0 + 1) * 4 + wr] = make_float4(cE1, cS1, cR1, cB1);
        }
    }
    #pragma unroll
    for (int s = 0; s < 4; s++) {
        #pragma unroll
        for (int o = 1; o <= 2; o <<= 1) {
            rE[s] += __shfl_xor_sync(0xffffffffu, rE[s], o);
            rS[s] += __shfl_xor_sync(0xffffffffu, rS[s], o);
            rR[s] += __shfl_xor_sync(0xffffffffu, rR[s], o);
            rB[s] = fmaxf(rB[s], __shfl_xor_sync(0xffffffffu, rB[s], o));
        }
    }
    if (lc2 == 0) {
        #pragma unroll
        for (int s = 0; s < 4; s++)
            rowPart[(wr * 32 + s * 8 + lr4) * 2 + wc] = make_float4(rE[s], rS[s], rR[s], rB[s]);
    }
    __syncthreads();
    if (tid < 128) {
        float4 a = rowPart[tid * 2], b2 = rowPart[tid * 2 + 1];
        int row = rowBase + tid;
        atomicAdd(&g_accE[row], a.x + b2.x);
        atomicAdd(&g_accS[row], a.y + b2.y);
        atomicAdd(&g_accR[row], a.z + b2.z);
        atomicMax(&g_accM[row], fenc(fmaxf(a.w, b2.w)));
    } else if (!isDiag) {
        int cc = tid - 128;
        float4 x0 = colPart[cc * 4 + 0], x1 = colPart[cc * 4 + 1];
        float4 x2 = colPart[cc * 4 + 2], x3 = colPart[cc * 4 + 3];
        int row = jBase + cc;
        atomicAdd(&g_accE[row], x0.x + x1.x + x2.x + x3.x);
        atomicAdd(&g_accS[row], x0.y + x1.y + x2.y + x3.y);
        atomicAdd(&g_accR[row], x0.z + x1.z + x2.z + x3.z);
        atomicMax(&g_accM[row], fenc(fmaxf(fmaxf(x0.w, x1.w), fmaxf(x2.w, x3.w))));
    }
}

// ---------------------------------------------------------------------------
// 128 blocks; block b finalizes rows b*32..b*32+31 from the atomic acc,
// emits per-block partials; the LAST block runs the final reduction.
__global__ void k_reduce(const int* __restrict__ tgt, float* __restrict__ out,
                         int N, int C) {
    __shared__ float rRb[32];
    __shared__ int   labb[32];
    __shared__ unsigned s_last;
    __shared__ float fld[24];
    int tid = threadIdx.x, warp = tid >> 5, lane = tid & 31;
    int bb = blockIdx.x;

    pdl_wait();   // PDL: k_main's atomics visible after this

    if (warp == 0) {
        int row = bb * 32 + lane;
        float E = g_accE[row], S = g_accS[row], R = g_accR[row];
        float bmx = fdec(g_accM[row]);
        float ce = g_rowCe[row];
        int lb = tgt[row];
        int cnt = g_cnt[lb];
        int msum = cnt - 1;
        float clc = 0.f;
        if (msum > 0)
            clc = S * 10.f / (float)msum - 10.f - logf(E + 1e-12f);
        float Bmax = fmaxf(0.f, bmx * 20.f);
        float rR = R * expf(20.f - Bmax) + (float)cnt * expf(-Bmax);
        rRb[lane] = rR;
        labb[lane] = lb;
        float s1 = clc, s2 = ce;
        #pragma unroll
        for (int o = 16; o; o >>= 1) {
            s1 += __shfl_xor_sync(0xffffffffu, s1, o);
            s2 += __shfl_xor_sync(0xffffffffu, s2, o);
        }
        if (lane == 0) { g_blk[bb * 24 + 1] = s1; g_blk[bb * 24 + 0] = s2; }
    }
    __syncthreads();
    if (tid >= 64 && tid < 64 + C) {
        int c = tid - 64;
        float s = 0.f;
        #pragma unroll
        for (int i = 0; i < 32; i++) s += (labb[i] == c) ? rRb[i] : 0.f;
        g_blk[bb * 24 + 2 + c] = s;
    }

    // ---- last-block-done final reduction ----
    __threadfence();
    __syncthreads();
    if (tid == 0) s_last = (atomicAdd(&g_done, 1u) == (unsigned)(gridDim.x - 1));
    __syncthreads();
    if (!s_last) return;

    for (int f = warp; f < 2 + C; f += 8) {
        float s = 0.f;
        #pragma unroll
        for (int k = 0; k < 4; k++) s += g_blk[(lane + k * 32) * 24 + f];
        #pragma unroll
        for (int o = 16; o; o >>= 1) s += __shfl_xor_sync(0xffffffffu, s, o);
        if (lane == 0) fld[f] = s;
    }
    __syncthreads();
    if (warp == 0) {
        bool has = (lane < C);
        int   cc = has ? g_cnt[lane] : 0;
        float Rc = has ? fld[2 + lane] : 0.f;
        float myc = (float)cc * (float)(N - cc);     // exact: <= 2^24
        float totalR = Rc, total_c = myc;
        #pragma unroll
        for (int o = 16; o; o >>= 1) {
            totalR  += __shfl_xor_sync(0xffffffffu, totalR, o);
            total_c += __shfl_xor_sync(0xffffffffu, total_c, o);
        }
        float ns = total_c - myc;
        unsigned nz = __ballot_sync(0xffffffffu, has && cc > 0 && ns != 0.f);
        bool all_zero = (nz == 0u);
        float term = 0.f;
        if (has && cc > 0) {
            float S = (N - cc > 0) ? (totalR - Rc + (float)cc * (float)N) : 0.f;
            float x = all_zero ? S : S / ((ns == 0.f) ? 1.0f : ns);
            term = (float)cc * logf(x + 1e-12f);
        }
        #pragma unroll
        for (int o = 16; o; o >>= 1) term += __shfl_xor_sync(0xffffffffu, term, o);
        if (lane == 0) {
            float ce_loss = -fld[0] / (float)N;
            float cl_loss = -fld[1] / (float)N;
            float triple  = term / (float)N;
            out[0] = 0.5f * ce_loss + 0.5f * cl_loss + 0.25f * triple;
            g_done = 0;                          // reset for next graph replay
        }
    }
    __syncthreads();
    if (tid < CLS_MAX) g_cnt[tid] = 0;           // leave zeroed for next call
}

// ---------------------------------------------------------------------------
extern "C" void kernel_launch(void* const* d_in, const int* in_sizes, int n_in,
                              void* d_out, int out_size) {
    const float* cls  = (const float*)d_in[0];
    const float* pred = (const float*)d_in[1];
    const int*   tgt  = (const int*)d_in[2];
    int N = in_sizes[2];
    int C = in_sizes[1] / N;
    float* out = (float*)d_out;

    k_pre<<<N / 16 + (N + 255) / 256, 256>>>(cls, pred, tgt, N, C);

    cudaFuncSetAttribute(k_main, cudaFuncAttributeMaxDynamicSharedMemorySize, SMEM_MAIN);

    // PDL launches: dependent grid prelaunched; griddepcontrol.wait inside
    // orders it after the upstream kernel's implicit completion trigger.
    cudaLaunchAttribute attr[1];
    attr[0].id = cudaLaunchAttributeProgrammaticStreamSerialization;
    attr[0].val.programmaticStreamSerializationAllowed = 1;

    {
        cudaLaunchConfig_t cfg = {};
        cfg.gridDim = dim3(NJT * (NJT + 1) / 2, 1, 1);
        cfg.blockDim = dim3(256, 1, 1);
        cfg.dynamicSmemBytes = SMEM_MAIN;
        cfg.attrs = attr;
        cfg.numAttrs = 1;
        cudaLaunchKernelEx(&cfg, k_main, tgt);
    }
    {
        cudaLaunchConfig_t cfg = {};
        cfg.gridDim = dim3(NN / 32, 1, 1);
        cfg.blockDim = dim3(256, 1, 1);
        cfg.dynamicSmemBytes = 0;
        cfg.attrs = attr;
        cfg.numAttrs = 1;
        cudaLaunchKernelEx(&cfg, k_reduce, tgt, out, NN, C);
    }
}